// round 14
// baseline (speedup 1.0000x reference)
#include <cuda_runtime.h>
#include <cuda_fp16.h>

#define NN   50000
#define EE   800000
#define INF  128
#define HH   4
#define OUTF 32
#define CC   128       // HH*OUTF
#define DSTR 64        // padded CSR stride (max in-degree; P(deg>=64) ~ 1e-20)

#define NSCAT 782      // ceil(800000/4/256) scatter blocks
#define NPROJ 782      // 391 node-tiles x 2 col-halves

// ---------------- scratch (device globals; no allocations) ----------------
__device__ __align__(16) __half g_hproj16[NN * CC];   // projected features, fp16
__device__ __align__(16) float  g_ssrc[NN * HH];
__device__ __align__(16) float  g_sdst[NN * HH];
__device__ int g_cnt[NN];           // in-degree (zero at load; k_gat re-zeros each run)
__device__ int g_esrc[NN * DSTR];   // padded CSR: src ids per dst

// ---------------- packed f32x2 helpers ----------------
__device__ __forceinline__ unsigned long long ffma2(unsigned long long a,
                                                    unsigned long long b,
                                                    unsigned long long c) {
    unsigned long long d;
    asm("fma.rn.f32x2 %0, %1, %2, %3;" : "=l"(d) : "l"(a), "l"(b), "l"(c));
    return d;
}
__device__ __forceinline__ void unpackf2(unsigned long long v, float& x, float& y) {
    asm("mov.b64 {%0, %1}, %2;" : "=f"(x), "=f"(y) : "l"(v));
}

// ---------------- K1: interleaved scatter + projection GEMM + node scores ----------------
// Odd bids: scatter. Even bids: 128-node x 64-col GEMM half-tile with
// pre-duplicated H pairs in smem (no per-FFMA2 pack instructions).
__global__ __launch_bounds__(256) void k_fused(const float* __restrict__ h,
                                               const int* __restrict__ ei,
                                               const float* __restrict__ W,
                                               const float* __restrict__ a) {
    // 18 float2 per row = 144 B: 16-byte aligned row stride (float4 stores OK)
    __shared__ __align__(16) float2 Hsd[128][18];  // [node][k] duplicated (h,h)
    __shared__ __align__(16) float  Ws[16][64];    // [k][col half]
    int tid = threadIdx.x;

    if (blockIdx.x & 1) {
        // ---- scatter ----
        int sb = blockIdx.x >> 1;
        int base = (sb * 256 + tid) * 4;
        if (base >= EE) return;
        int4 s = *(const int4*)&ei[base];
        int4 d = *(const int4*)&ei[EE + base];
        int p0 = min(atomicAdd(&g_cnt[d.x], 1), DSTR - 1);
        int p1 = min(atomicAdd(&g_cnt[d.y], 1), DSTR - 1);
        int p2 = min(atomicAdd(&g_cnt[d.z], 1), DSTR - 1);
        int p3 = min(atomicAdd(&g_cnt[d.w], 1), DSTR - 1);
        g_esrc[d.x * DSTR + p0] = s.x;
        g_esrc[d.y * DSTR + p1] = s.y;
        g_esrc[d.z * DSTR + p2] = s.z;
        g_esrc[d.w * DSTR + p3] = s.w;
        return;
    }

    int pb = blockIdx.x >> 1;
    int c = pb & 1;                  // col half: heads {2c, 2c+1}
    int node0 = (pb >> 1) * 128;
    int tx = tid & 15;
    int ty = tid >> 4;
    int tx2 = tx * 2;

    unsigned long long acc2[8][2];
#pragma unroll
    for (int n = 0; n < 8; n++) { acc2[n][0] = 0ull; acc2[n][1] = 0ull; }

    int ln  = tid >> 1;               // Hsd loader node
    int lkb = (tid & 1) * 8;          // Hsd loader k base (0 or 8, even)
    int wk  = tid >> 4;               // Ws loader k
    int wc0 = (tid & 15) * 4;         // Ws loader col base (local)
    int gcol = c * 64 + wc0;
    int whd = gcol >> 5, wo0 = gcol & 31;

    for (int kb = 0; kb < INF; kb += 16) {
        {
            int node = node0 + ln;
            float4 a0, a1;
            if (node < NN) {
                a0 = *(const float4*)&h[node * INF + kb + lkb];
                a1 = *(const float4*)&h[node * INF + kb + lkb + 4];
            } else {
                a0 = make_float4(0, 0, 0, 0);
                a1 = a0;
            }
            // duplicated pairs: (h,h) per k, 2 per STS.128 (16B-aligned)
            *(float4*)&Hsd[ln][lkb + 0] = make_float4(a0.x, a0.x, a0.y, a0.y);
            *(float4*)&Hsd[ln][lkb + 2] = make_float4(a0.z, a0.z, a0.w, a0.w);
            *(float4*)&Hsd[ln][lkb + 4] = make_float4(a1.x, a1.x, a1.y, a1.y);
            *(float4*)&Hsd[ln][lkb + 6] = make_float4(a1.z, a1.z, a1.w, a1.w);
        }
        *(float4*)&Ws[wk][wc0] = *(const float4*)&W[(whd * INF + kb + wk) * OUTF + wo0];
        __syncthreads();
#pragma unroll
        for (int kk = 0; kk < 16; kk++) {
            unsigned long long w2[2];
            w2[0] = *(const unsigned long long*)&Ws[kk][tx2];
            w2[1] = *(const unsigned long long*)&Ws[kk][32 + tx2];
#pragma unroll
            for (int n = 0; n < 8; n++) {
                unsigned long long h2 = *(const unsigned long long*)&Hsd[ty * 8 + n][kk];
                acc2[n][0] = ffma2(h2, w2[0], acc2[n][0]);
                acc2[n][1] = ffma2(h2, w2[1], acc2[n][1]);
            }
        }
        __syncthreads();
    }

    // store hproj (fp16) for this col half
#pragma unroll
    for (int n = 0; n < 8; n++) {
        int node = node0 + ty * 8 + n;
        if (node < NN) {
#pragma unroll
            for (int j = 0; j < 2; j++) {
                float lo, hi;
                unpackf2(acc2[n][j], lo, hi);
                *(__half2*)&g_hproj16[node * CC + c * 64 + j * 32 + tx2] =
                    __floats2half2_rn(lo, hi);
            }
        }
    }

    // ---- score epilogue for heads 2c, 2c+1 ----
    float asv[2][2], adv[2][2];
#pragma unroll
    for (int j = 0; j < 2; j++) {
        int head = c * 2 + j;
        float2 v0 = *(const float2*)&a[head * 64 + tx2];
        float2 v1 = *(const float2*)&a[head * 64 + 32 + tx2];
        asv[j][0] = v0.x; asv[j][1] = v0.y;
        adv[j][0] = v1.x; adv[j][1] = v1.y;
    }
#pragma unroll
    for (int n = 0; n < 8; n++) {
        float ps[2], pd[2];
#pragma unroll
        for (int j = 0; j < 2; j++) {
            float lo, hi;
            unpackf2(acc2[n][j], lo, hi);
            ps[j] = lo * asv[j][0] + hi * asv[j][1];
            pd[j] = lo * adv[j][0] + hi * adv[j][1];
        }
#pragma unroll
        for (int off = 8; off; off >>= 1) {
#pragma unroll
            for (int j = 0; j < 2; j++) {
                ps[j] += __shfl_xor_sync(0xFFFFFFFFu, ps[j], off);
                pd[j] += __shfl_xor_sync(0xFFFFFFFFu, pd[j], off);
            }
        }
        if (tx == 0) {
            int node = node0 + ty * 8 + n;
            if (node < NN) {
                *(float2*)&g_ssrc[node * HH + c * 2] = make_float2(ps[0], ps[1]);
                *(float2*)&g_sdst[node * HH + c * 2] = make_float2(pd[0], pd[1]);
            }
        }
    }
}

// ---------------- K2: block-per-node softmax + aggregation + ELU ----------------
// Phase A: per-slot {offset, weight} packed per head -> one LDS.128 per edge in
// the hot loop. Phase B: 4 warps, strided slots, 4-deep fp16 gather batches.
__global__ __launch_bounds__(128) void k_gat(float* __restrict__ out) {
    const unsigned FULL = 0xFFFFFFFFu;
    __shared__ __align__(16) uint4 sOW[DSTR][HH];   // {off, w_bits, 0, 0} : 4 KB
    __shared__ float sDen[HH];
    __shared__ __align__(16) float sAcc[4][CC];

    int node = blockIdx.x;
    int tid  = threadIdx.x;
    int w    = tid >> 5;
    int lane = tid & 31;
    int hd   = lane >> 3;

    int cnt = min(g_cnt[node], DSTR);
    float4 sd4 = *(const float4*)&g_sdst[node * HH];

    // Phase A: slot j = w + lane*4 (lanes 0..15 of each warp cover 64 slots)
    int j = w + lane * 4;
    if (j < DSTR) {
        if (j < cnt) {
            int src = g_esrc[node * DSTR + j];
            float4 ss = *(const float4*)&g_ssrc[src * HH];
            float wv[4];
            float x;
            x = ss.x + sd4.x; x = x > 0.0f ? x : 0.2f * x; wv[0] = __expf(x);
            x = ss.y + sd4.y; x = x > 0.0f ? x : 0.2f * x; wv[1] = __expf(x);
            x = ss.z + sd4.z; x = x > 0.0f ? x : 0.2f * x; wv[2] = __expf(x);
            x = ss.w + sd4.w; x = x > 0.0f ? x : 0.2f * x; wv[3] = __expf(x);
            unsigned off = (unsigned)(src * CC);
#pragma unroll
            for (int q = 0; q < 4; q++)
                sOW[j][q] = make_uint4(off, __float_as_uint(wv[q]), 0u, 0u);
        } else {
#pragma unroll
            for (int q = 0; q < 4; q++)
                sOW[j][q] = make_uint4(0u, 0u, 0u, 0u);
        }
    }
    __syncthreads();
    if (tid == 0) g_cnt[node] = 0;   // restore zero invariant (all reads done)

    // denominator: warp w reduces head w over zero-filled slots (once per block)
    float dsum = __uint_as_float(sOW[lane][w].y) +
                 __uint_as_float(sOW[lane + 32][w].y);
#pragma unroll
    for (int off = 16; off; off >>= 1)
        dsum += __shfl_xor_sync(FULL, dsum, off);
    if (lane == 0) sDen[w] = dsum;

    // Phase B: warp w accumulates slots j % 4 == w, 4-deep batches
    int nw = (cnt > w) ? ((cnt - w + 3) >> 2) : 0;
    int laneoff = lane * 4;
    float4 acc = make_float4(0, 0, 0, 0);
    int i = 0;
    for (; i + 4 <= nw; i += 4) {
        uint4 ow[4];
        uint2 v[4];
#pragma unroll
        for (int q = 0; q < 4; q++)
            ow[q] = sOW[w + (i + q) * 4][hd];
#pragma unroll
        for (int q = 0; q < 4; q++)
            v[q] = *(const uint2*)&g_hproj16[ow[q].x + laneoff];
#pragma unroll
        for (int q = 0; q < 4; q++) {
            float wt = __uint_as_float(ow[q].y);
            float2 f01 = __half22float2(*(__half2*)&v[q].x);
            float2 f23 = __half22float2(*(__half2*)&v[q].y);
            acc.x = fmaf(wt, f01.x, acc.x);
            acc.y = fmaf(wt, f01.y, acc.y);
            acc.z = fmaf(wt, f23.x, acc.z);
            acc.w = fmaf(wt, f23.y, acc.w);
        }
    }
    for (; i < nw; i++) {
        uint4 ow = sOW[w + i * 4][hd];
        uint2 raw = *(const uint2*)&g_hproj16[ow.x + laneoff];
        float wt = __uint_as_float(ow.y);
        float2 f01 = __half22float2(*(__half2*)&raw.x);
        float2 f23 = __half22float2(*(__half2*)&raw.y);
        acc.x = fmaf(wt, f01.x, acc.x);
        acc.y = fmaf(wt, f01.y, acc.y);
        acc.z = fmaf(wt, f23.x, acc.z);
        acc.w = fmaf(wt, f23.y, acc.w);
    }
    *(float4*)&sAcc[w][laneoff] = acc;
    __syncthreads();

    // epilogue: thread tid -> channel tid (coalesced 512B store)
    int ch = tid;
    float v = sAcc[0][ch] + sAcc[1][ch] + sAcc[2][ch] + sAcc[3][ch];
    float inv = 1.0f / fmaxf(sDen[ch >> 5], 1e-16f);
    float r = v * inv;
    r = r > 0.0f ? r : (__expf(r) - 1.0f);
    out[node * CC + ch] = r;
}

extern "C" void kernel_launch(void* const* d_in, const int* in_sizes, int n_in,
                              void* d_out, int out_size) {
    const float* h  = (const float*)d_in[0];
    const int*   ei = (const int*)d_in[1];
    const float* W  = (const float*)d_in[2];
    const float* a  = (const float*)d_in[3];
    float* out = (float*)d_out;

    k_fused<<<NSCAT + NPROJ, 256>>>(h, ei, W, a);
    k_gat<<<NN, 128>>>(out);
}

// round 15
// speedup vs baseline: 1.6362x; 1.6362x over previous
#include <cuda_runtime.h>
#include <cuda_fp16.h>

#define NN   50000
#define EE   800000
#define INF  128
#define HH   4
#define OUTF 32
#define CC   128       // HH*OUTF
#define DSTR 64        // padded CSR stride (max in-degree; P(deg>=64) ~ 1e-20)

#define NSCAT 782      // ceil(800000/4/256) scatter blocks
#define NPROJ 782      // 391 node-tiles x 2 col-halves

// ---------------- scratch (device globals; no allocations) ----------------
__device__ __align__(16) __half g_hproj16[NN * CC];   // projected features, fp16
__device__ __align__(16) float  g_ssrc[NN * HH];
__device__ __align__(16) float  g_sdst[NN * HH];
__device__ int g_cnt[NN];           // in-degree (zero at load; k_gat re-zeros each run)
__device__ int g_esrc[NN * DSTR];   // padded CSR: src ids per dst

// ---------------- packed f32x2 helpers ----------------
__device__ __forceinline__ unsigned long long ffma2(unsigned long long a,
                                                    unsigned long long b,
                                                    unsigned long long c) {
    unsigned long long d;
    asm("fma.rn.f32x2 %0, %1, %2, %3;" : "=l"(d) : "l"(a), "l"(b), "l"(c));
    return d;
}
__device__ __forceinline__ void unpackf2(unsigned long long v, float& x, float& y) {
    asm("mov.b64 {%0, %1}, %2;" : "=f"(x), "=f"(y) : "l"(v));
}
__device__ __forceinline__ unsigned long long packf2(float x, float y) {
    unsigned long long d;
    asm("mov.b64 %0, {%1, %2};" : "=l"(d) : "f"(x), "f"(y));
    return d;
}

// ---------------- K1: interleaved scatter + projection GEMM + node scores ----------------
// (exact R11 version — measured ~53 us)
__global__ __launch_bounds__(256) void k_fused(const float* __restrict__ h,
                                               const int* __restrict__ ei,
                                               const float* __restrict__ W,
                                               const float* __restrict__ a) {
    __shared__ __align__(16) float Hs[128][17];   // [node][k] (+pad)
    __shared__ __align__(16) float Ws[16][64];    // [k][col half]
    int tid = threadIdx.x;

    if (blockIdx.x & 1) {
        // ---- scatter ----
        int sb = blockIdx.x >> 1;
        int base = (sb * 256 + tid) * 4;
        if (base >= EE) return;
        int4 s = *(const int4*)&ei[base];
        int4 d = *(const int4*)&ei[EE + base];
        int p0 = min(atomicAdd(&g_cnt[d.x], 1), DSTR - 1);
        int p1 = min(atomicAdd(&g_cnt[d.y], 1), DSTR - 1);
        int p2 = min(atomicAdd(&g_cnt[d.z], 1), DSTR - 1);
        int p3 = min(atomicAdd(&g_cnt[d.w], 1), DSTR - 1);
        g_esrc[d.x * DSTR + p0] = s.x;
        g_esrc[d.y * DSTR + p1] = s.y;
        g_esrc[d.z * DSTR + p2] = s.z;
        g_esrc[d.w * DSTR + p3] = s.w;
        return;
    }

    int pb = blockIdx.x >> 1;
    int c = pb & 1;                  // col half: heads {2c, 2c+1}
    int node0 = (pb >> 1) * 128;
    int tx = tid & 15;
    int ty = tid >> 4;
    int tx2 = tx * 2;

    unsigned long long acc2[8][2];
#pragma unroll
    for (int n = 0; n < 8; n++) { acc2[n][0] = 0ull; acc2[n][1] = 0ull; }

    int ln  = tid >> 1;               // Hs loader node
    int lkb = (tid & 1) * 8;          // Hs loader k base
    int wk  = tid >> 4;               // Ws loader k
    int wc0 = (tid & 15) * 4;         // Ws loader col base (local)
    int gcol = c * 64 + wc0;
    int whd = gcol >> 5, wo0 = gcol & 31;

    for (int kb = 0; kb < INF; kb += 16) {
        {
            int node = node0 + ln;
            float4 a0, a1;
            if (node < NN) {
                a0 = *(const float4*)&h[node * INF + kb + lkb];
                a1 = *(const float4*)&h[node * INF + kb + lkb + 4];
            } else {
                a0 = make_float4(0, 0, 0, 0);
                a1 = a0;
            }
            Hs[ln][lkb + 0] = a0.x; Hs[ln][lkb + 1] = a0.y;
            Hs[ln][lkb + 2] = a0.z; Hs[ln][lkb + 3] = a0.w;
            Hs[ln][lkb + 4] = a1.x; Hs[ln][lkb + 5] = a1.y;
            Hs[ln][lkb + 6] = a1.z; Hs[ln][lkb + 7] = a1.w;
        }
        *(float4*)&Ws[wk][wc0] = *(const float4*)&W[(whd * INF + kb + wk) * OUTF + wo0];
        __syncthreads();
#pragma unroll
        for (int kk = 0; kk < 16; kk++) {
            unsigned long long w2[2];
            w2[0] = *(const unsigned long long*)&Ws[kk][tx2];
            w2[1] = *(const unsigned long long*)&Ws[kk][32 + tx2];
#pragma unroll
            for (int n = 0; n < 8; n++) {
                float hv = Hs[ty * 8 + n][kk];
                unsigned long long h2 = packf2(hv, hv);
                acc2[n][0] = ffma2(h2, w2[0], acc2[n][0]);
                acc2[n][1] = ffma2(h2, w2[1], acc2[n][1]);
            }
        }
        __syncthreads();
    }

    // store hproj (fp16) for this col half
#pragma unroll
    for (int n = 0; n < 8; n++) {
        int node = node0 + ty * 8 + n;
        if (node < NN) {
#pragma unroll
            for (int j = 0; j < 2; j++) {
                float lo, hi;
                unpackf2(acc2[n][j], lo, hi);
                *(__half2*)&g_hproj16[node * CC + c * 64 + j * 32 + tx2] =
                    __floats2half2_rn(lo, hi);
            }
        }
    }

    // ---- score epilogue for heads 2c, 2c+1 ----
    float asv[2][2], adv[2][2];
#pragma unroll
    for (int j = 0; j < 2; j++) {
        int head = c * 2 + j;
        float2 v0 = *(const float2*)&a[head * 64 + tx2];
        float2 v1 = *(const float2*)&a[head * 64 + 32 + tx2];
        asv[j][0] = v0.x; asv[j][1] = v0.y;
        adv[j][0] = v1.x; adv[j][1] = v1.y;
    }
#pragma unroll
    for (int n = 0; n < 8; n++) {
        float ps[2], pd[2];
#pragma unroll
        for (int j = 0; j < 2; j++) {
            float lo, hi;
            unpackf2(acc2[n][j], lo, hi);
            ps[j] = lo * asv[j][0] + hi * asv[j][1];
            pd[j] = lo * adv[j][0] + hi * adv[j][1];
        }
#pragma unroll
        for (int off = 8; off; off >>= 1) {
#pragma unroll
            for (int j = 0; j < 2; j++) {
                ps[j] += __shfl_xor_sync(0xFFFFFFFFu, ps[j], off);
                pd[j] += __shfl_xor_sync(0xFFFFFFFFu, pd[j], off);
            }
        }
        if (tx == 0) {
            int node = node0 + ty * 8 + n;
            if (node < NN) {
                *(float2*)&g_ssrc[node * HH + c * 2] = make_float2(ps[0], ps[1]);
                *(float2*)&g_sdst[node * HH + c * 2] = make_float2(pd[0], pd[1]);
            }
        }
    }
}

// ---------------- K2: block-per-node (2 warps) softmax + aggregation + ELU ----------------
// R11 structure with half the warps: fixed per-node cost drops ~2x while the
// hot loop total is unchanged (issue-bound kernel).
__global__ __launch_bounds__(64) void k_gat(float* __restrict__ out) {
    const unsigned FULL = 0xFFFFFFFFu;
    __shared__ int   sOff[DSTR];        // src * CC
    __shared__ float sW[DSTR][HH];
    __shared__ float sDen[HH];
    __shared__ __align__(16) float sAcc[2][CC];

    int node = blockIdx.x;
    int tid  = threadIdx.x;
    int w    = tid >> 5;
    int lane = tid & 31;
    int hd   = lane >> 3;

    int cnt = min(g_cnt[node], DSTR);
    float4 sd4 = *(const float4*)&g_sdst[node * HH];

    // Phase A: slot j = w + lane*2; all 64 lanes cover all 64 slots
    int j = w + lane * 2;
    if (j < cnt) {
        int src = g_esrc[node * DSTR + j];
        float4 ss = *(const float4*)&g_ssrc[src * HH];
        float4 w0;
        float x;
        x = ss.x + sd4.x; x = x > 0.0f ? x : 0.2f * x; w0.x = __expf(x);
        x = ss.y + sd4.y; x = x > 0.0f ? x : 0.2f * x; w0.y = __expf(x);
        x = ss.z + sd4.z; x = x > 0.0f ? x : 0.2f * x; w0.z = __expf(x);
        x = ss.w + sd4.w; x = x > 0.0f ? x : 0.2f * x; w0.w = __expf(x);
        sOff[j] = src * CC;
        *(float4*)&sW[j][0] = w0;
    } else {
        sOff[j] = 0;
        *(float4*)&sW[j][0] = make_float4(0, 0, 0, 0);
    }
    __syncthreads();
    if (tid == 0) g_cnt[node] = 0;   // restore zero invariant (all reads done)

    // denominator: warp w reduces heads {2w, 2w+1} over zero-filled slots
    float2 d0 = *(const float2*)&sW[lane][2 * w];
    float2 d1 = *(const float2*)&sW[lane + 32][2 * w];
    float2 ds = make_float2(d0.x + d1.x, d0.y + d1.y);
#pragma unroll
    for (int off = 16; off; off >>= 1) {
        ds.x += __shfl_xor_sync(FULL, ds.x, off);
        ds.y += __shfl_xor_sync(FULL, ds.y, off);
    }
    if (lane == 0) *(float2*)&sDen[2 * w] = ds;

    // Phase B: warp w accumulates slots j % 2 == w, 4-deep batches
    int nw = (cnt > w) ? ((cnt - w + 1) >> 1) : 0;
    int laneoff = lane * 4;
    float4 acc = make_float4(0, 0, 0, 0);
    int i = 0;
    for (; i + 4 <= nw; i += 4) {
        int   o[4];
        float wt[4];
        uint2 v[4];
#pragma unroll
        for (int q = 0; q < 4; q++) {
            int slot = w + (i + q) * 2;
            o[q] = sOff[slot];
            wt[q] = sW[slot][hd];
        }
#pragma unroll
        for (int q = 0; q < 4; q++)
            v[q] = *(const uint2*)&g_hproj16[o[q] + laneoff];
#pragma unroll
        for (int q = 0; q < 4; q++) {
            float2 f01 = __half22float2(*(__half2*)&v[q].x);
            float2 f23 = __half22float2(*(__half2*)&v[q].y);
            acc.x = fmaf(wt[q], f01.x, acc.x);
            acc.y = fmaf(wt[q], f01.y, acc.y);
            acc.z = fmaf(wt[q], f23.x, acc.z);
            acc.w = fmaf(wt[q], f23.y, acc.w);
        }
    }
    for (; i < nw; i++) {
        int slot = w + i * 2;
        int o = sOff[slot];
        float wt = sW[slot][hd];
        uint2 raw = *(const uint2*)&g_hproj16[o + laneoff];
        float2 f01 = __half22float2(*(__half2*)&raw.x);
        float2 f23 = __half22float2(*(__half2*)&raw.y);
        acc.x = fmaf(wt, f01.x, acc.x);
        acc.y = fmaf(wt, f01.y, acc.y);
        acc.z = fmaf(wt, f23.x, acc.z);
        acc.w = fmaf(wt, f23.y, acc.w);
    }
    *(float4*)&sAcc[w][laneoff] = acc;
    __syncthreads();

    // epilogue: thread tid -> channels {2*tid, 2*tid+1} (same head), float2 store
    int ch = tid * 2;
    float2 p0 = *(const float2*)&sAcc[0][ch];
    float2 p1 = *(const float2*)&sAcc[1][ch];
    float inv = 1.0f / fmaxf(sDen[ch >> 5], 1e-16f);
    float2 r;
    r.x = (p0.x + p1.x) * inv;
    r.y = (p0.y + p1.y) * inv;
    r.x = r.x > 0.0f ? r.x : (__expf(r.x) - 1.0f);
    r.y = r.y > 0.0f ? r.y : (__expf(r.y) - 1.0f);
    *(float2*)&out[node * CC + ch] = r;
}

extern "C" void kernel_launch(void* const* d_in, const int* in_sizes, int n_in,
                              void* d_out, int out_size) {
    const float* h  = (const float*)d_in[0];
    const int*   ei = (const int*)d_in[1];
    const float* W  = (const float*)d_in[2];
    const float* a  = (const float*)d_in[3];
    float* out = (float*)d_out;

    k_fused<<<NSCAT + NPROJ, 256>>>(h, ei, W, a);
    k_gat<<<NN, 64>>>(out);
}